// round 14
// baseline (speedup 1.0000x reference)
#include <cuda_runtime.h>
#include <cuda_bf16.h>
#include <cstdint>

// Problem constants
#define Lq   2048
#define Bb   4
#define Ee   1024
#define Hh   16
#define HD   64
#define BHh  64            // Bb*Hh
#define Mrows (Lq*Bb)      // 8192
#define SEG  ((size_t)BHh * Lq * HD)     // 8388608
#define ME   ((size_t)Mrows * Ee)        // 8388608
#define EE   ((size_t)Ee * Ee)           // 1048576

// Interleaved fragment-native layout: per row, per k-group of 16, per tc(0..3):
// 16B chunk = [hi(k0),hi(k0+1),hi(k0+8),hi(k0+9), lo(k0),lo(k0+1),lo(k0+8),lo(k0+9)]
// where k0 = kg*16 + tc*2. Row stride = 2*K elements.
__device__ __nv_bfloat16 g_x[3 * ME * 2];      // q,k,v activations (prep)
__device__ __nv_bfloat16 g_w[4 * EE * 2];      // in_proj_weight rows 0..3071, out_w rows 3072..4095
__device__ __nv_bfloat16 g_o[SEG * 2];         // attention output (row = token, K-dim = 64 hd)
// attention operands keep the plain split layout
__device__ __nv_bfloat16 g_qkvh[3 * SEG], g_qkvl[3 * SEG];

typedef unsigned long long u64;

// ---------------------------------------------------------------------------
// helpers
// ---------------------------------------------------------------------------
__device__ __forceinline__ uint32_t smem_u32(const void* p) {
    uint32_t a;
    asm("{ .reg .u64 t; cvta.to.shared.u64 t, %1; cvt.u32.u64 %0, t; }"
        : "=r"(a) : "l"(p));
    return a;
}
#define CP16(dst, src) asm volatile("cp.async.cg.shared.global [%0], [%1], 16;" :: "r"(dst), "l"(src))
#define CP_COMMIT()    asm volatile("cp.async.commit_group;" ::: "memory")
#define CP_WAIT(n)     asm volatile("cp.async.wait_group %0;" :: "n"(n) : "memory")

__device__ __forceinline__ void mma_bf16(float* c, const uint32_t* a, const uint32_t* b) {
    asm volatile(
        "mma.sync.aligned.m16n8k16.row.col.f32.bf16.bf16.f32 "
        "{%0,%1,%2,%3}, {%4,%5,%6,%7}, {%8,%9}, {%0,%1,%2,%3};"
        : "+f"(c[0]), "+f"(c[1]), "+f"(c[2]), "+f"(c[3])
        : "r"(a[0]), "r"(a[1]), "r"(a[2]), "r"(a[3]), "r"(b[0]), "r"(b[1]));
}

__device__ __forceinline__ void split_bf(float x, unsigned short& h, unsigned short& l) {
    h = __bfloat16_as_ushort(__float2bfloat16(x));
    float r = x - __bfloat162float(__ushort_as_bfloat16(h));
    l = __bfloat16_as_ushort(__float2bfloat16(r));
}
__device__ __forceinline__ void split_pack2(float f0, float f1, uint32_t& hi, uint32_t& lo) {
    unsigned short h0, h1, l0, l1;
    split_bf(f0, h0, l0); split_bf(f1, h1, l1);
    hi = (uint32_t)h0 | ((uint32_t)h1 << 16);
    lo = (uint32_t)l0 | ((uint32_t)l1 << 16);
}
__device__ __forceinline__ uint32_t get16(const uint4& v, int j) {
    uint32_t w = ((j >> 1) == 0) ? v.x : ((j >> 1) == 1) ? v.y : ((j >> 1) == 2) ? v.z : v.w;
    return (j & 1) ? (w >> 16) : (w & 0xffffu);
}

// ---------------------------------------------------------------------------
// prep: split + permute into fragment-native interleaved layout.
// One 16B output chunk (4 source floats) per thread.
// ---------------------------------------------------------------------------
#define NCH ((3 * ME + 4 * EE) / 4)     // 7340032 chunks
__global__ __launch_bounds__(256)
void prep_kernel(const float* __restrict__ q, const float* __restrict__ k,
                 const float* __restrict__ v, const float* __restrict__ w,
                 const float* __restrict__ ow)
{
    size_t ci = (size_t)blockIdx.x * 256 + threadIdx.x;
    if (ci >= NCH) return;

    const float* srow;
    __nv_bfloat16* drow;
    int within;                          // 0..255: kg = within>>2, tc = within&3
    if (ci < 3 * ME / 4) {
        size_t z = ci / (ME / 4), o = ci - z * (ME / 4);
        size_t row = o >> 8; within = (int)(o & 255);
        srow = (z == 0 ? q : z == 1 ? k : v) + row * Ee;
        drow = g_x + z * (ME * 2) + row * 2048;
    } else {
        size_t o = ci - 3 * ME / 4;      // EE chunks over 4096 weight rows
        size_t row = o >> 8; within = (int)(o & 255);
        srow = (row < 3 * (size_t)Ee) ? (w + row * Ee) : (ow + (row - 3 * Ee) * Ee);
        drow = g_w + row * 2048;
    }
    const int kg = within >> 2, tc = within & 3;
    const int k0 = kg * 16 + tc * 2;
    float2 f0 = *(const float2*)(srow + k0);
    float2 f1 = *(const float2*)(srow + k0 + 8);
    uint32_t h0, l0, h1, l1;
    split_pack2(f0.x, f0.y, h0, l0);
    split_pack2(f1.x, f1.y, h1, l1);
    *(uint4*)(drow + kg * 32 + tc * 8) = make_uint4(h0, h1, l0, l1);
}

// ---------------------------------------------------------------------------
// GEMM on mma.sync bf16x3, fragment-native LDS.128 loads. CTA 128x128,
// K-step 32, 2-stage cp.async, 192B smem rows (conflict-free LDS.128),
// smem 96KB -> 2 CTAs/SM.
// MODE 0: QKV projection (writes split Q,K,V), MODE 1: out projection.
// ---------------------------------------------------------------------------
#define GROW  192                    // 128B data (hi+lo for 32 k) + 64B pad
#define TPA   (128 * GROW)           // 24576 (one combined hi/lo tile)
#define STG   (2 * TPA)              // 49152 (A + B)
#define SMEM_T (2 * STG)             // 98304
#define NIT   32                     // 1024 / 32

template<int MODE>
__global__ __launch_bounds__(256, 2)
void gemm_tc(const float* __restrict__ bias, float* __restrict__ outp)
{
    extern __shared__ __align__(128) char smem[];
    const uint32_t sbase = smem_u32(smem);

    const int z   = (MODE == 0) ? blockIdx.z : 0;
    const int bm  = blockIdx.y * 128;
    const int bn  = blockIdx.x * 128;
    const int tid = threadIdx.x;
    const int wid  = tid >> 5;
    const int lane = tid & 31;
    const int wm = wid & 3;
    const int wn = wid >> 2;

    const int r    = tid >> 1;       // 0..127 tile row
    const int half = tid & 1;        // 64B half of a 128B row

    // global row bases (elements, interleaved layout: 2*K per row)
    const __nv_bfloat16* a_row;
    if (MODE == 0) {
        a_row = g_x + z * (ME * 2) + (size_t)(bm + r) * 2048 + half * 32;
    } else {
        const int mrow = bm + r;
        const int lA = mrow >> 2, bA = mrow & 3;
        a_row = g_o + ((size_t)bA * Hh * Lq + lA) * 128 + half * 32;   // + head term per iter
    }
    const __nv_bfloat16* b_row = g_w + (size_t)((MODE == 0 ? z * Ee : 3 * Ee) + bn + r) * 2048 + half * 32;

    const uint32_t dst_r = sbase + r * GROW + half * 64;

    float acc[2][8][4];
#pragma unroll
    for (int i = 0; i < 2; i++)
#pragma unroll
        for (int j = 0; j < 8; j++)
#pragma unroll
            for (int t = 0; t < 4; t++) acc[i][j][t] = 0.0f;

    auto load_stage = [&](int it, int s) {
        const uint32_t d = dst_r + s * STG;
        const __nv_bfloat16* pa = (MODE == 0)
            ? a_row + (size_t)it * 64
            : a_row + (size_t)(it >> 1) * ((size_t)Lq * 128) + (size_t)(it & 1) * 64;
        const __nv_bfloat16* pb = b_row + (size_t)it * 64;
        CP16(d + 0,          pa);      CP16(d + 16,          pa + 8);
        CP16(d + 32,         pa + 16); CP16(d + 48,          pa + 24);
        CP16(d + TPA + 0,    pb);      CP16(d + TPA + 16,    pb + 8);
        CP16(d + TPA + 32,   pb + 16); CP16(d + TPA + 48,    pb + 24);
    };

    const int g  = lane >> 2;
    const int tc = lane & 3;

    load_stage(0, 0); CP_COMMIT();

    for (int it = 0; it < NIT; it++) {
        CP_WAIT(0);
        __syncthreads();
        if (it + 1 < NIT) { load_stage(it + 1, (it + 1) & 1); CP_COMMIT(); }

        const char* sa = smem + (it & 1) * STG;
        const char* sbm = sa + TPA;

#pragma unroll
        for (int ks = 0; ks < 2; ks++) {
            const int coff = ks * 64 + tc * 16;
            uint32_t ah[2][4], al[2][4];
#pragma unroll
            for (int mt = 0; mt < 2; mt++) {
                const int r0 = wm * 32 + mt * 16 + g;
                uint4 c0 = *(const uint4*)(sa + r0 * GROW + coff);
                uint4 c1 = *(const uint4*)(sa + (r0 + 8) * GROW + coff);
                ah[mt][0] = c0.x; ah[mt][1] = c1.x; ah[mt][2] = c0.y; ah[mt][3] = c1.y;
                al[mt][0] = c0.z; al[mt][1] = c1.z; al[mt][2] = c0.w; al[mt][3] = c1.w;
            }
#pragma unroll
            for (int nt = 0; nt < 8; nt++) {
                const int rn = wn * 64 + nt * 8 + g;
                uint4 cb = *(const uint4*)(sbm + rn * GROW + coff);
                uint32_t bh[2] = { cb.x, cb.y };
                uint32_t bl[2] = { cb.z, cb.w };
#pragma unroll
                for (int mt = 0; mt < 2; mt++) {
                    mma_bf16(acc[mt][nt], ah[mt], bh);
                    mma_bf16(acc[mt][nt], ah[mt], bl);
                    mma_bf16(acc[mt][nt], al[mt], bh);
                }
            }
        }
    }

    const float scale = (MODE == 0 && z == 0) ? 0.125f : 1.0f;
#pragma unroll
    for (int mt = 0; mt < 2; mt++) {
#pragma unroll
        for (int half_m = 0; half_m < 2; half_m++) {
            const int m = bm + wm * 32 + mt * 16 + g + half_m * 8;
#pragma unroll
            for (int nt = 0; nt < 8; nt++) {
                const int n = bn + wn * 64 + nt * 8 + tc * 2;
                const float c0 = acc[mt][nt][half_m * 2 + 0];
                const float c1 = acc[mt][nt][half_m * 2 + 1];
                if (MODE == 0) {
                    const int l = m >> 2, b = m & 3;
                    const int h = n >> 6, d = n & 63;
                    float v0 = scale * (c0 + bias[z * Ee + n]);
                    float v1 = scale * (c1 + bias[z * Ee + n + 1]);
                    uint32_t hi, lo;
                    split_pack2(v0, v1, hi, lo);
                    size_t addr = (size_t)z * SEG + ((size_t)(b * Hh + h) * Lq + l) * HD + d;
                    *(uint32_t*)&g_qkvh[addr] = hi;
                    *(uint32_t*)&g_qkvl[addr] = lo;
                } else {
                    float2 t;
                    t.x = c0 + bias[n];
                    t.y = c1 + bias[n + 1];
                    *(float2*)&outp[(size_t)m * Ee + n] = t;
                }
            }
        }
    }
}

// ---------------------------------------------------------------------------
// Flash attention on mma.sync bf16x3, K-tile 64 tokens, 2-stage pipeline
// (73.7KB smem -> 2 CTAs/SM). Unchanged from R13 except epilogue writes g_o
// in the interleaved fragment-native layout for gemm<1>.
// ---------------------------------------------------------------------------
#define TKT    64
#define KROW   144
#define VTROW  144
#define SM_KH  0
#define SM_KL  (SM_KH + TKT * KROW)       // 9216
#define SM_VTH (SM_KL + TKT * KROW)       // 18432
#define SM_VTL (SM_VTH + 64 * VTROW)      // 27648
#define AT_STG (SM_VTL + 64 * VTROW)      // 36864 per stage
#define SM_ATTN (2 * AT_STG)              // 73728

__global__ __launch_bounds__(256, 2)
void attn_mma()
{
    extern __shared__ __align__(128) char smem[];
    const uint32_t sb = smem_u32(smem);

    const int head = blockIdx.y;
    const int q0   = blockIdx.x * 128;
    const int tid  = threadIdx.x;
    const int wid  = tid >> 5;
    const int lane = tid & 31;
    const int g    = lane >> 2;
    const int tc   = lane & 3;

    const __nv_bfloat16* Qh = g_qkvh;
    const __nv_bfloat16* Ql = g_qkvl;
    const __nv_bfloat16* Kh = g_qkvh + SEG;
    const __nv_bfloat16* Kl = g_qkvl + SEG;
    const __nv_bfloat16* Vh = g_qkvh + 2 * SEG;
    const __nv_bfloat16* Vl = g_qkvl + 2 * SEG;

    // Q fragments in registers (per warp: 16 rows x 64 hd)
    uint32_t qa_h[4][4], qa_l[4][4];
    {
        const size_t r0 = (size_t)head * Lq + q0 + wid * 16 + g;
        const size_t r1 = r0 + 8;
#pragma unroll
        for (int ks = 0; ks < 4; ks++) {
            const int c0 = ks * 16 + tc * 2;
            qa_h[ks][0] = *(const uint32_t*)(Qh + r0 * HD + c0);
            qa_h[ks][1] = *(const uint32_t*)(Qh + r1 * HD + c0);
            qa_h[ks][2] = *(const uint32_t*)(Qh + r0 * HD + c0 + 8);
            qa_h[ks][3] = *(const uint32_t*)(Qh + r1 * HD + c0 + 8);
            qa_l[ks][0] = *(const uint32_t*)(Ql + r0 * HD + c0);
            qa_l[ks][1] = *(const uint32_t*)(Ql + r1 * HD + c0);
            qa_l[ks][2] = *(const uint32_t*)(Ql + r0 * HD + c0 + 8);
            qa_l[ks][3] = *(const uint32_t*)(Ql + r1 * HD + c0 + 8);
        }
    }

    float O[8][4];
#pragma unroll
    for (int i = 0; i < 8; i++)
#pragma unroll
        for (int j = 0; j < 4; j++) O[i][j] = 0.0f;
    float m0 = -1e30f, m1 = -1e30f, l0 = 0.0f, l1 = 0.0f;

    // coop-load assignments
    const int kr = tid >> 2;          // 0..63 K rows
    const int kq = tid & 3;           // 32B quarter
    const int vsp  = tid >> 7;        // V split (0=hi,1=lo)
    const int vidx = tid & 127;
    const int tb   = (vidx & 15) * 4; // token block (4 tokens)
    const int hb   = (vidx >> 4) * 8; // hd block (8 dims)
    const __nv_bfloat16* Vsrc = vsp ? Vl : Vh;
    const uint32_t vbase = sb + (vsp ? SM_VTL : SM_VTH);

    auto load_k = [&](int kt, int s) {
        const uint32_t dk = sb + s * AT_STG + kr * KROW + kq * 32;
        const size_t src = ((size_t)head * Lq + kt + kr) * HD + kq * 16;
        CP16(dk + SM_KH, Kh + src); CP16(dk + SM_KH + 16, Kh + src + 8);
        CP16(dk + SM_KL, Kl + src); CP16(dk + SM_KL + 16, Kl + src + 8);
        CP_COMMIT();
    };
    auto load_v = [&](int kt, uint4* vv) {
#pragma unroll
        for (int t = 0; t < 4; t++)
            vv[t] = *(const uint4*)(Vsrc + ((size_t)head * Lq + kt + tb + t) * HD + hb);
    };
    auto store_v = [&](int s, const uint4* vv) {
        const uint32_t vdst = vbase + s * AT_STG;
#pragma unroll
        for (int j = 0; j < 8; j++) {
#pragma unroll
            for (int tp = 0; tp < 2; tp++) {
                uint32_t w0 = get16(vv[2 * tp], j);
                uint32_t w1 = get16(vv[2 * tp + 1], j);
                uint32_t pk = w0 | (w1 << 16);
                const uint32_t a = vdst + (hb + j) * VTROW + (tb + 2 * tp) * 2;
                asm volatile("st.shared.b32 [%0], %1;" :: "r"(a), "r"(pk) : "memory");
            }
        }
    };

    // prologue: tile 0 into stage 0
    {
        uint4 vv[4];
        load_k(0, 0);
        load_v(0, vv);
        store_v(0, vv);
    }

    const int NTILE = Lq / TKT;      // 32
    for (int t = 0; t < NTILE; t++) {
        CP_WAIT(0);
        __syncthreads();
        const int cur = t & 1;
        const int nxt = (t + 1) & 1;
        if (t + 1 < NTILE) load_k((t + 1) * TKT, nxt);

        const char* skh = smem + cur * AT_STG + SM_KH;

        // S = Q K^T (8 ntiles of 8 tokens)
        float s[8][4];
#pragma unroll
        for (int nt = 0; nt < 8; nt++) {
            float c[4] = {0.f, 0.f, 0.f, 0.f};
#pragma unroll
            for (int ks = 0; ks < 4; ks++) {
                const char* pb = skh + (nt * 8 + g) * KROW + ks * 32 + tc * 4;
                uint32_t bh[2], bl[2];
                bh[0] = *(const uint32_t*)(pb);
                bh[1] = *(const uint32_t*)(pb + 16);
                bl[0] = *(const uint32_t*)(pb + (SM_KL - SM_KH));
                bl[1] = *(const uint32_t*)(pb + (SM_KL - SM_KH) + 16);
                mma_bf16(c, qa_h[ks], bh);
                mma_bf16(c, qa_h[ks], bl);
                mma_bf16(c, qa_l[ks], bh);
            }
            s[nt][0] = c[0]; s[nt][1] = c[1]; s[nt][2] = c[2]; s[nt][3] = c[3];
        }

        // prefetch V of next tile into registers
        uint4 vv[4];
        if (t + 1 < NTILE) load_v((t + 1) * TKT, vv);

        // online softmax (quad-reduced row max)
        float tm0 = -1e30f, tm1 = -1e30f;
#pragma unroll
        for (int nt = 0; nt < 8; nt++) {
            tm0 = fmaxf(tm0, fmaxf(s[nt][0], s[nt][1]));
            tm1 = fmaxf(tm1, fmaxf(s[nt][2], s[nt][3]));
        }
        tm0 = fmaxf(tm0, __shfl_xor_sync(0xffffffffu, tm0, 1));
        tm0 = fmaxf(tm0, __shfl_xor_sync(0xffffffffu, tm0, 2));
        tm1 = fmaxf(tm1, __shfl_xor_sync(0xffffffffu, tm1, 1));
        tm1 = fmaxf(tm1, __shfl_xor_sync(0xffffffffu, tm1, 2));

        const float nm0 = fmaxf(m0, tm0);
        const float nm1 = fmaxf(m1, tm1);
        const float cor0 = __expf(m0 - nm0);
        const float cor1 = __expf(m1 - nm1);
        m0 = nm0; m1 = nm1;
        l0 *= cor0; l1 *= cor1;
#pragma unroll
        for (int nt = 0; nt < 8; nt++) {
            O[nt][0] *= cor0; O[nt][1] *= cor0;
            O[nt][2] *= cor1; O[nt][3] *= cor1;
        }

        // exp + pack P fragments (C-frag layout == A-frag layout)
        uint32_t pah[4][4], pal[4][4];
#pragma unroll
        for (int ks = 0; ks < 4; ks++) {
            const float p0 = __expf(s[2 * ks][0] - m0);
            const float p1 = __expf(s[2 * ks][1] - m0);
            const float p2 = __expf(s[2 * ks][2] - m1);
            const float p3 = __expf(s[2 * ks][3] - m1);
            const float p4 = __expf(s[2 * ks + 1][0] - m0);
            const float p5 = __expf(s[2 * ks + 1][1] - m0);
            const float p6 = __expf(s[2 * ks + 1][2] - m1);
            const float p7 = __expf(s[2 * ks + 1][3] - m1);
            l0 += p0 + p1 + p4 + p5;
            l1 += p2 + p3 + p6 + p7;
            split_pack2(p0, p1, pah[ks][0], pal[ks][0]);
            split_pack2(p2, p3, pah[ks][1], pal[ks][1]);
            split_pack2(p4, p5, pah[ks][2], pal[ks][2]);
            split_pack2(p6, p7, pah[ks][3], pal[ks][3]);
        }

        // O += P V (8 hd ntiles x 4 ksteps of 16 tokens)
        const char* svh = smem + cur * AT_STG + SM_VTH;
#pragma unroll
        for (int nt = 0; nt < 8; nt++) {
#pragma unroll
            for (int ks = 0; ks < 4; ks++) {
                const char* pv = svh + (nt * 8 + g) * VTROW + ks * 32 + tc * 4;
                uint32_t vh2[2], vl2[2];
                vh2[0] = *(const uint32_t*)(pv);
                vh2[1] = *(const uint32_t*)(pv + 16);
                vl2[0] = *(const uint32_t*)(pv + (SM_VTL - SM_VTH));
                vl2[1] = *(const uint32_t*)(pv + (SM_VTL - SM_VTH) + 16);
                mma_bf16(O[nt], pah[ks], vh2);
                mma_bf16(O[nt], pah[ks], vl2);
                mma_bf16(O[nt], pal[ks], vh2);
            }
        }

        // scatter prefetched V into next stage (visible after next barrier)
        if (t + 1 < NTILE) store_v(nxt, vv);
    }

    // finalize: quad-reduce l, normalize, write g_o in interleaved layout
    l0 += __shfl_xor_sync(0xffffffffu, l0, 1);
    l0 += __shfl_xor_sync(0xffffffffu, l0, 2);
    l1 += __shfl_xor_sync(0xffffffffu, l1, 1);
    l1 += __shfl_xor_sync(0xffffffffu, l1, 2);
    const float inv0 = 1.0f / l0;
    const float inv1 = 1.0f / l1;

    const size_t r0 = (size_t)head * Lq + q0 + wid * 16 + g;
    const size_t r1 = r0 + 8;
#pragma unroll
    for (int nt = 0; nt < 8; nt++) {
        const int kg = nt >> 1, c8 = nt & 1;
        const int off = kg * 32 + tc * 8 + c8 * 2;     // elements within 128-elem row
        uint32_t hi, lo;
        split_pack2(O[nt][0] * inv0, O[nt][1] * inv0, hi, lo);
        *(uint32_t*)&g_o[r0 * 128 + off]     = hi;
        *(uint32_t*)&g_o[r0 * 128 + off + 4] = lo;
        split_pack2(O[nt][2] * inv1, O[nt][3] * inv1, hi, lo);
        *(uint32_t*)&g_o[r1 * 128 + off]     = hi;
        *(uint32_t*)&g_o[r1 * 128 + off + 4] = lo;
    }
}

// ---------------------------------------------------------------------------
// Launch
// Inputs: 0=q, 1=k, 2=v, 3=in_proj_weight, 4=in_proj_bias, 5=out_w, 6=out_b
// ---------------------------------------------------------------------------
extern "C" void kernel_launch(void* const* d_in, const int* in_sizes, int n_in,
                              void* d_out, int out_size)
{
    const float* q  = (const float*)d_in[0];
    const float* k  = (const float*)d_in[1];
    const float* v  = (const float*)d_in[2];
    const float* w  = (const float*)d_in[3];
    const float* bi = (const float*)d_in[4];
    const float* ow = (const float*)d_in[5];
    const float* ob = (const float*)d_in[6];
    float* out = (float*)d_out;

    static bool configured = false;
    if (!configured) {
        cudaFuncSetAttribute(gemm_tc<0>, cudaFuncAttributeMaxDynamicSharedMemorySize, SMEM_T);
        cudaFuncSetAttribute(gemm_tc<1>, cudaFuncAttributeMaxDynamicSharedMemorySize, SMEM_T);
        cudaFuncSetAttribute(attn_mma,   cudaFuncAttributeMaxDynamicSharedMemorySize, SM_ATTN);
        configured = true;
    }

    prep_kernel<<<(unsigned)((NCH + 255) / 256), 256>>>(q, k, v, w, ow);

    dim3 gp(Ee / 128, Mrows / 128, 3);
    gemm_tc<0><<<gp, 256, SMEM_T>>>(bi, nullptr);

    dim3 ga(Lq / 128, BHh);
    attn_mma<<<ga, 256, SM_ATTN>>>();

    dim3 go(Ee / 128, Mrows / 128);
    gemm_tc<1><<<go, 256, SMEM_T>>>(ob, out);
}

// round 16
// speedup vs baseline: 1.2321x; 1.2321x over previous
#include <cuda_runtime.h>
#include <cuda_bf16.h>
#include <cuda_fp16.h>
#include <cstdint>

// Problem constants
#define Lq   2048
#define Bb   4
#define Ee   1024
#define Hh   16
#define HD   64
#define BHh  64            // Bb*Hh
#define Mrows (Lq*Bb)      // 8192
#define SEG  ((size_t)BHh * Lq * HD)     // 8388608
#define ME   ((size_t)Mrows * Ee)        // 8388608
#define EE   ((size_t)Ee * Ee)           // 1048576

// bf16 split operands
__device__ __nv_bfloat16 g_xh[3 * ME], g_xl[3 * ME];       // q,k,v activations (prep)
__device__ __nv_bfloat16 g_wh[4 * EE], g_wl[4 * EE];       // in_proj_weight (3EE) + out_w (EE)
__device__ __nv_bfloat16 g_qkvh[3 * SEG], g_qkvl[3 * SEG]; // projected Q,K (V region unused)
__device__ __half        g_vf[SEG];                        // projected V, plain fp16
__device__ __nv_bfloat16 g_oh[SEG], g_ol[SEG];             // attention output

typedef unsigned long long u64;

// ---------------------------------------------------------------------------
// helpers
// ---------------------------------------------------------------------------
__device__ __forceinline__ uint32_t smem_u32(const void* p) {
    uint32_t a;
    asm("{ .reg .u64 t; cvta.to.shared.u64 t, %1; cvt.u32.u64 %0, t; }"
        : "=r"(a) : "l"(p));
    return a;
}
#define CP16(dst, src) asm volatile("cp.async.cg.shared.global [%0], [%1], 16;" :: "r"(dst), "l"(src))
#define CP_COMMIT()    asm volatile("cp.async.commit_group;" ::: "memory")
#define CP_WAIT(n)     asm volatile("cp.async.wait_group %0;" :: "n"(n) : "memory")

__device__ __forceinline__ void mma_bf16(float* c, const uint32_t* a, const uint32_t* b) {
    asm volatile(
        "mma.sync.aligned.m16n8k16.row.col.f32.bf16.bf16.f32 "
        "{%0,%1,%2,%3}, {%4,%5,%6,%7}, {%8,%9}, {%0,%1,%2,%3};"
        : "+f"(c[0]), "+f"(c[1]), "+f"(c[2]), "+f"(c[3])
        : "r"(a[0]), "r"(a[1]), "r"(a[2]), "r"(a[3]), "r"(b[0]), "r"(b[1]));
}
__device__ __forceinline__ void mma_f16(float* c, const uint32_t* a, const uint32_t* b) {
    asm volatile(
        "mma.sync.aligned.m16n8k16.row.col.f32.f16.f16.f32 "
        "{%0,%1,%2,%3}, {%4,%5,%6,%7}, {%8,%9}, {%0,%1,%2,%3};"
        : "+f"(c[0]), "+f"(c[1]), "+f"(c[2]), "+f"(c[3])
        : "r"(a[0]), "r"(a[1]), "r"(a[2]), "r"(a[3]), "r"(b[0]), "r"(b[1]));
}

__device__ __forceinline__ void split_bf(float x, unsigned short& h, unsigned short& l) {
    h = __bfloat16_as_ushort(__float2bfloat16(x));
    float r = x - __bfloat162float(__ushort_as_bfloat16(h));
    l = __bfloat16_as_ushort(__float2bfloat16(r));
}
__device__ __forceinline__ void split_pack2(float f0, float f1, uint32_t& hi, uint32_t& lo) {
    unsigned short h0, h1, l0, l1;
    split_bf(f0, h0, l0); split_bf(f1, h1, l1);
    hi = (uint32_t)h0 | ((uint32_t)h1 << 16);
    lo = (uint32_t)l0 | ((uint32_t)l1 << 16);
}
__device__ __forceinline__ uint32_t pack_h2(float f0, float f1) {
    __half2 h = __floats2half2_rn(f0, f1);
    return *(uint32_t*)&h;
}
__device__ __forceinline__ uint32_t geth(const uint2& v, int j) {
    uint32_t w = (j >> 1) ? v.y : v.x;
    return (j & 1) ? (w >> 16) : (w & 0xffffu);
}

// ---------------------------------------------------------------------------
// prep: split activations + weights into bf16 hi/lo. One float4 per thread.
// ---------------------------------------------------------------------------
#define NX4 ((3 * ME + 4 * EE) / 4)
__global__ __launch_bounds__(256)
void prep_kernel(const float* __restrict__ q, const float* __restrict__ k,
                 const float* __restrict__ v, const float* __restrict__ w,
                 const float* __restrict__ ow)
{
    size_t i4 = (size_t)blockIdx.x * 256 + threadIdx.x;
    if (i4 >= NX4) return;
    size_t base = i4 * 4;
    const float* src;
    __nv_bfloat16 *dh, *dl;
    if (base < 3 * ME) {
        size_t z = base / ME, off = base - z * ME;
        src = (z == 0 ? q : z == 1 ? k : v) + off;
        dh = g_xh + base; dl = g_xl + base;
    } else {
        size_t off = base - 3 * ME;
        src = (off < 3 * EE) ? (w + off) : (ow + (off - 3 * EE));
        dh = g_wh + off; dl = g_wl + off;
    }
    float4 f = *(const float4*)src;
    uint32_t h0, l0, h1, l1;
    split_pack2(f.x, f.y, h0, l0);
    split_pack2(f.z, f.w, h1, l1);
    *(uint2*)dh = make_uint2(h0, h1);
    *(uint2*)dl = make_uint2(l0, l1);
}

// ---------------------------------------------------------------------------
// GEMM on mma.sync bf16x3 (scalar LDS frags). CTA 128x128, K-step 32,
// 2-stage cp.async, smem 80KB -> 2 CTAs/SM. (R13 structure.)
// MODE 0: QKV projection (Q,K split bf16; V plain fp16), MODE 1: out proj.
// ---------------------------------------------------------------------------
#define GROW  80
#define TP    (128 * GROW)
#define STG   (4 * TP)
#define SMEM_T (2 * STG)
#define NIT   32

template<int MODE>
__global__ __launch_bounds__(256, 2)
void gemm_tc(const float* __restrict__ bias, float* __restrict__ outp)
{
    extern __shared__ __align__(128) char smem[];
    const uint32_t sbase = smem_u32(smem);

    const int z   = (MODE == 0) ? blockIdx.z : 0;
    const int bm  = blockIdx.y * 128;
    const int bn  = blockIdx.x * 128;
    const int tid = threadIdx.x;
    const int wid  = tid >> 5;
    const int lane = tid & 31;
    const int wm = wid & 3;
    const int wn = wid >> 2;

    const int r    = tid >> 1;
    const int half = tid & 1;

    const __nv_bfloat16 *a_h, *a_l;
    if (MODE == 0) {
        size_t arow = (size_t)z * ME + (size_t)(bm + r) * Ee + half * 16;
        a_h = g_xh + arow; a_l = g_xl + arow;
    } else {
        const int mrow = bm + r;
        const int lA = mrow >> 2, bA = mrow & 3;
        size_t arow = ((size_t)bA * Hh * Lq + lA) * HD + half * 16;
        a_h = g_oh + arow; a_l = g_ol + arow;
    }
    const size_t brow = (size_t)((MODE == 0 ? z * Ee : 3 * Ee) + bn + r) * Ee + half * 16;
    const __nv_bfloat16* b_h = g_wh + brow;
    const __nv_bfloat16* b_l = g_wl + brow;

    const uint32_t dst_r = sbase + r * GROW + half * 32;

    float acc[2][8][4];
#pragma unroll
    for (int i = 0; i < 2; i++)
#pragma unroll
        for (int j = 0; j < 8; j++)
#pragma unroll
            for (int t = 0; t < 4; t++) acc[i][j][t] = 0.0f;

    auto load_stage = [&](int it, int s) {
        const uint32_t d = dst_r + s * STG;
        const size_t aoff = (MODE == 0)
            ? (size_t)it * 32
            : (size_t)(it >> 1) * ((size_t)Lq * HD) + (size_t)(it & 1) * 32;
        const size_t boff = (size_t)it * 32;
        const __nv_bfloat16* pa_h = a_h + aoff;
        const __nv_bfloat16* pa_l = a_l + aoff;
        const __nv_bfloat16* pb_h = b_h + boff;
        const __nv_bfloat16* pb_l = b_l + boff;
        CP16(d + 0 * TP,      pa_h); CP16(d + 0 * TP + 16, pa_h + 8);
        CP16(d + 1 * TP,      pa_l); CP16(d + 1 * TP + 16, pa_l + 8);
        CP16(d + 2 * TP,      pb_h); CP16(d + 2 * TP + 16, pb_h + 8);
        CP16(d + 3 * TP,      pb_l); CP16(d + 3 * TP + 16, pb_l + 8);
    };

    const int g  = lane >> 2;
    const int tc = lane & 3;

    load_stage(0, 0); CP_COMMIT();

    for (int it = 0; it < NIT; it++) {
        CP_WAIT(0);
        __syncthreads();
        if (it + 1 < NIT) { load_stage(it + 1, (it + 1) & 1); CP_COMMIT(); }

        const char* sa_h = smem + (it & 1) * STG + 0 * TP;
        const char* sa_l = smem + (it & 1) * STG + 1 * TP;
        const char* sb_h = smem + (it & 1) * STG + 2 * TP;
        const char* sb_l = smem + (it & 1) * STG + 3 * TP;

#pragma unroll
        for (int ks = 0; ks < 2; ks++) {
            const int cbyte = ks * 32 + tc * 4;
            uint32_t ah[2][4], al[2][4];
#pragma unroll
            for (int mt = 0; mt < 2; mt++) {
                const int r0 = wm * 32 + mt * 16 + g;
                const char* ph = sa_h + r0 * GROW + cbyte;
                const char* pl = sa_l + r0 * GROW + cbyte;
                ah[mt][0] = *(const uint32_t*)(ph);
                ah[mt][1] = *(const uint32_t*)(ph + 8 * GROW);
                ah[mt][2] = *(const uint32_t*)(ph + 16);
                ah[mt][3] = *(const uint32_t*)(ph + 8 * GROW + 16);
                al[mt][0] = *(const uint32_t*)(pl);
                al[mt][1] = *(const uint32_t*)(pl + 8 * GROW);
                al[mt][2] = *(const uint32_t*)(pl + 16);
                al[mt][3] = *(const uint32_t*)(pl + 8 * GROW + 16);
            }
#pragma unroll
            for (int nt = 0; nt < 8; nt++) {
                const int rn = wn * 64 + nt * 8 + g;
                const char* pbh = sb_h + rn * GROW + cbyte;
                const char* pbl = sb_l + rn * GROW + cbyte;
                uint32_t bh[2], bl[2];
                bh[0] = *(const uint32_t*)(pbh);
                bh[1] = *(const uint32_t*)(pbh + 16);
                bl[0] = *(const uint32_t*)(pbl);
                bl[1] = *(const uint32_t*)(pbl + 16);
#pragma unroll
                for (int mt = 0; mt < 2; mt++) {
                    mma_bf16(acc[mt][nt], ah[mt], bh);
                    mma_bf16(acc[mt][nt], ah[mt], bl);
                    mma_bf16(acc[mt][nt], al[mt], bh);
                }
            }
        }
    }

    const float scale = (MODE == 0 && z == 0) ? 0.125f : 1.0f;
#pragma unroll
    for (int mt = 0; mt < 2; mt++) {
#pragma unroll
        for (int half_m = 0; half_m < 2; half_m++) {
            const int m = bm + wm * 32 + mt * 16 + g + half_m * 8;
#pragma unroll
            for (int nt = 0; nt < 8; nt++) {
                const int n = bn + wn * 64 + nt * 8 + tc * 2;
                const float c0 = acc[mt][nt][half_m * 2 + 0];
                const float c1 = acc[mt][nt][half_m * 2 + 1];
                if (MODE == 0) {
                    const int l = m >> 2, b = m & 3;
                    const int h = n >> 6, d = n & 63;
                    float v0 = scale * (c0 + bias[z * Ee + n]);
                    float v1 = scale * (c1 + bias[z * Ee + n + 1]);
                    size_t addr = ((size_t)(b * Hh + h) * Lq + l) * HD + d;
                    if (z == 2) {
                        *(uint32_t*)&g_vf[addr] = pack_h2(v0, v1);
                    } else {
                        uint32_t hi, lo;
                        split_pack2(v0, v1, hi, lo);
                        *(uint32_t*)&g_qkvh[(size_t)z * SEG + addr] = hi;
                        *(uint32_t*)&g_qkvl[(size_t)z * SEG + addr] = lo;
                    }
                } else {
                    float2 t;
                    t.x = c0 + bias[n];
                    t.y = c1 + bias[n + 1];
                    *(float2*)&outp[(size_t)m * Ee + n] = t;
                }
            }
        }
    }
}

// ---------------------------------------------------------------------------
// Flash attention: QK on bf16x3, PV on plain fp16 (1 MMA). K-tile 64,
// 2-stage pipeline, smem 55KB -> 2 CTAs/SM.
// ---------------------------------------------------------------------------
#define TKT    64
#define KROW   144
#define VTROW  144
#define SM_KH  0
#define SM_KL  (SM_KH + TKT * KROW)       // 9216
#define SM_VT  (SM_KL + TKT * KROW)       // 18432
#define AT_STG (SM_VT + 64 * VTROW)       // 27648 per stage
#define SM_ATTN (2 * AT_STG)              // 55296

__global__ __launch_bounds__(256, 2)
void attn_mma()
{
    extern __shared__ __align__(128) char smem[];
    const uint32_t sb = smem_u32(smem);

    const int head = blockIdx.y;
    const int q0   = blockIdx.x * 128;
    const int tid  = threadIdx.x;
    const int wid  = tid >> 5;
    const int lane = tid & 31;
    const int g    = lane >> 2;
    const int tc   = lane & 3;

    const __nv_bfloat16* Qh = g_qkvh;
    const __nv_bfloat16* Ql = g_qkvl;
    const __nv_bfloat16* Kh = g_qkvh + SEG;
    const __nv_bfloat16* Kl = g_qkvl + SEG;

    // Q fragments in registers (per warp: 16 rows x 64 hd)
    uint32_t qa_h[4][4], qa_l[4][4];
    {
        const size_t r0 = (size_t)head * Lq + q0 + wid * 16 + g;
        const size_t r1 = r0 + 8;
#pragma unroll
        for (int ks = 0; ks < 4; ks++) {
            const int c0 = ks * 16 + tc * 2;
            qa_h[ks][0] = *(const uint32_t*)(Qh + r0 * HD + c0);
            qa_h[ks][1] = *(const uint32_t*)(Qh + r1 * HD + c0);
            qa_h[ks][2] = *(const uint32_t*)(Qh + r0 * HD + c0 + 8);
            qa_h[ks][3] = *(const uint32_t*)(Qh + r1 * HD + c0 + 8);
            qa_l[ks][0] = *(const uint32_t*)(Ql + r0 * HD + c0);
            qa_l[ks][1] = *(const uint32_t*)(Ql + r1 * HD + c0);
            qa_l[ks][2] = *(const uint32_t*)(Ql + r0 * HD + c0 + 8);
            qa_l[ks][3] = *(const uint32_t*)(Ql + r1 * HD + c0 + 8);
        }
    }

    float O[8][4];
#pragma unroll
    for (int i = 0; i < 8; i++)
#pragma unroll
        for (int j = 0; j < 4; j++) O[i][j] = 0.0f;
    float m0 = -1e30f, m1 = -1e30f, l0 = 0.0f, l1 = 0.0f;

    // coop-load assignments
    const int kr = tid >> 2;          // 0..63 K rows
    const int kq = tid & 3;           // 32B quarter
    const int tb = (tid & 15) * 4;    // V token block (4 tokens)
    const int hb = (tid >> 4) * 4;    // V hd block (4 dims)

    auto load_k = [&](int kt, int s) {
        const uint32_t dk = sb + s * AT_STG + kr * KROW + kq * 32;
        const size_t src = ((size_t)head * Lq + kt + kr) * HD + kq * 16;
        CP16(dk + SM_KH, Kh + src); CP16(dk + SM_KH + 16, Kh + src + 8);
        CP16(dk + SM_KL, Kl + src); CP16(dk + SM_KL + 16, Kl + src + 8);
        CP_COMMIT();
    };
    auto load_v = [&](int kt, uint2* vv) {
#pragma unroll
        for (int t = 0; t < 4; t++)
            vv[t] = *(const uint2*)(g_vf + ((size_t)head * Lq + kt + tb + t) * HD + hb);
    };
    auto store_v = [&](int s, const uint2* vv) {
        const uint32_t vdst = sb + s * AT_STG + SM_VT;
#pragma unroll
        for (int j = 0; j < 4; j++) {
            uint32_t p01 = geth(vv[0], j) | (geth(vv[1], j) << 16);
            uint32_t p23 = geth(vv[2], j) | (geth(vv[3], j) << 16);
            const uint32_t a = vdst + (hb + j) * VTROW + tb * 2;
            asm volatile("st.shared.b32 [%0], %1;" :: "r"(a), "r"(p01) : "memory");
            asm volatile("st.shared.b32 [%0], %1;" :: "r"(a + 4), "r"(p23) : "memory");
        }
    };

    // prologue: tile 0 into stage 0
    {
        uint2 vv[4];
        load_k(0, 0);
        load_v(0, vv);
        store_v(0, vv);
    }

    const int NTILE = Lq / TKT;      // 32
    for (int t = 0; t < NTILE; t++) {
        CP_WAIT(0);
        __syncthreads();
        const int cur = t & 1;
        const int nxt = (t + 1) & 1;
        if (t + 1 < NTILE) load_k((t + 1) * TKT, nxt);

        const char* skh = smem + cur * AT_STG + SM_KH;

        // S = Q K^T (8 ntiles of 8 tokens), bf16x3
        float s[8][4];
#pragma unroll
        for (int nt = 0; nt < 8; nt++) {
            float c[4] = {0.f, 0.f, 0.f, 0.f};
#pragma unroll
            for (int ks = 0; ks < 4; ks++) {
                const char* pb = skh + (nt * 8 + g) * KROW + ks * 32 + tc * 4;
                uint32_t bh[2], bl[2];
                bh[0] = *(const uint32_t*)(pb);
                bh[1] = *(const uint32_t*)(pb + 16);
                bl[0] = *(const uint32_t*)(pb + (SM_KL - SM_KH));
                bl[1] = *(const uint32_t*)(pb + (SM_KL - SM_KH) + 16);
                mma_bf16(c, qa_h[ks], bh);
                mma_bf16(c, qa_h[ks], bl);
                mma_bf16(c, qa_l[ks], bh);
            }
            s[nt][0] = c[0]; s[nt][1] = c[1]; s[nt][2] = c[2]; s[nt][3] = c[3];
        }

        // prefetch V of next tile into registers
        uint2 vv[4];
        if (t + 1 < NTILE) load_v((t + 1) * TKT, vv);

        // online softmax (quad-reduced row max)
        float tm0 = -1e30f, tm1 = -1e30f;
#pragma unroll
        for (int nt = 0; nt < 8; nt++) {
            tm0 = fmaxf(tm0, fmaxf(s[nt][0], s[nt][1]));
            tm1 = fmaxf(tm1, fmaxf(s[nt][2], s[nt][3]));
        }
        tm0 = fmaxf(tm0, __shfl_xor_sync(0xffffffffu, tm0, 1));
        tm0 = fmaxf(tm0, __shfl_xor_sync(0xffffffffu, tm0, 2));
        tm1 = fmaxf(tm1, __shfl_xor_sync(0xffffffffu, tm1, 1));
        tm1 = fmaxf(tm1, __shfl_xor_sync(0xffffffffu, tm1, 2));

        const float nm0 = fmaxf(m0, tm0);
        const float nm1 = fmaxf(m1, tm1);
        const float cor0 = __expf(m0 - nm0);
        const float cor1 = __expf(m1 - nm1);
        m0 = nm0; m1 = nm1;
        l0 *= cor0; l1 *= cor1;
#pragma unroll
        for (int nt = 0; nt < 8; nt++) {
            O[nt][0] *= cor0; O[nt][1] *= cor0;
            O[nt][2] *= cor1; O[nt][3] *= cor1;
        }

        // exp + pack P fragments as fp16 (C-frag layout == A-frag layout)
        uint32_t pa[4][4];
#pragma unroll
        for (int ks = 0; ks < 4; ks++) {
            const float p0 = __expf(s[2 * ks][0] - m0);
            const float p1 = __expf(s[2 * ks][1] - m0);
            const float p2 = __expf(s[2 * ks][2] - m1);
            const float p3 = __expf(s[2 * ks][3] - m1);
            const float p4 = __expf(s[2 * ks + 1][0] - m0);
            const float p5 = __expf(s[2 * ks + 1][1] - m0);
            const float p6 = __expf(s[2 * ks + 1][2] - m1);
            const float p7 = __expf(s[2 * ks + 1][3] - m1);
            l0 += p0 + p1 + p4 + p5;
            l1 += p2 + p3 + p6 + p7;
            pa[ks][0] = pack_h2(p0, p1);
            pa[ks][1] = pack_h2(p2, p3);
            pa[ks][2] = pack_h2(p4, p5);
            pa[ks][3] = pack_h2(p6, p7);
        }

        // O += P V (fp16 single pass: 8 hd ntiles x 4 ksteps of 16 tokens)
        const char* svt = smem + cur * AT_STG + SM_VT;
#pragma unroll
        for (int nt = 0; nt < 8; nt++) {
#pragma unroll
            for (int ks = 0; ks < 4; ks++) {
                const char* pv = svt + (nt * 8 + g) * VTROW + ks * 32 + tc * 4;
                uint32_t v2[2];
                v2[0] = *(const uint32_t*)(pv);
                v2[1] = *(const uint32_t*)(pv + 16);
                mma_f16(O[nt], pa[ks], v2);
            }
        }

        // scatter prefetched V into next stage (visible after next barrier)
        if (t + 1 < NTILE) store_v(nxt, vv);
    }

    // finalize: quad-reduce l, normalize, write split-bf16 O
    l0 += __shfl_xor_sync(0xffffffffu, l0, 1);
    l0 += __shfl_xor_sync(0xffffffffu, l0, 2);
    l1 += __shfl_xor_sync(0xffffffffu, l1, 1);
    l1 += __shfl_xor_sync(0xffffffffu, l1, 2);
    const float inv0 = 1.0f / l0;
    const float inv1 = 1.0f / l1;

    const size_t r0 = (size_t)head * Lq + q0 + wid * 16 + g;
    const size_t r1 = r0 + 8;
#pragma unroll
    for (int nt = 0; nt < 8; nt++) {
        const int col = nt * 8 + tc * 2;
        uint32_t hi, lo;
        split_pack2(O[nt][0] * inv0, O[nt][1] * inv0, hi, lo);
        *(uint32_t*)&g_oh[r0 * HD + col] = hi;
        *(uint32_t*)&g_ol[r0 * HD + col] = lo;
        split_pack2(O[nt][2] * inv1, O[nt][3] * inv1, hi, lo);
        *(uint32_t*)&g_oh[r1 * HD + col] = hi;
        *(uint32_t*)&g_ol[r1 * HD + col] = lo;
    }
}

// ---------------------------------------------------------------------------
// Launch
// Inputs: 0=q, 1=k, 2=v, 3=in_proj_weight, 4=in_proj_bias, 5=out_w, 6=out_b
// ---------------------------------------------------------------------------
extern "C" void kernel_launch(void* const* d_in, const int* in_sizes, int n_in,
                              void* d_out, int out_size)
{
    const float* q  = (const float*)d_in[0];
    const float* k  = (const float*)d_in[1];
    const float* v  = (const float*)d_in[2];
    const float* w  = (const float*)d_in[3];
    const float* bi = (const float*)d_in[4];
    const float* ow = (const float*)d_in[5];
    const float* ob = (const float*)d_in[6];
    float* out = (float*)d_out;

    static bool configured = false;
    if (!configured) {
        cudaFuncSetAttribute(gemm_tc<0>, cudaFuncAttributeMaxDynamicSharedMemorySize, SMEM_T);
        cudaFuncSetAttribute(gemm_tc<1>, cudaFuncAttributeMaxDynamicSharedMemorySize, SMEM_T);
        cudaFuncSetAttribute(attn_mma,   cudaFuncAttributeMaxDynamicSharedMemorySize, SM_ATTN);
        configured = true;
    }

    prep_kernel<<<(unsigned)((NX4 + 255) / 256), 256>>>(q, k, v, w, ow);

    dim3 gp(Ee / 128, Mrows / 128, 3);
    gemm_tc<0><<<gp, 256, SMEM_T>>>(bi, nullptr);

    dim3 ga(Lq / 128, BHh);
    attn_mma<<<ga, 256, SM_ATTN>>>();

    dim3 go(Ee / 128, Mrows / 128);
    gemm_tc<1><<<go, 256, SMEM_T>>>(ob, out);
}

// round 17
// speedup vs baseline: 2.1535x; 1.7479x over previous
#include <cuda_runtime.h>
#include <cuda_bf16.h>
#include <cuda_fp16.h>
#include <cstdint>

// Problem constants
#define Lq   2048
#define Bb   4
#define Ee   1024
#define Hh   16
#define HD   64
#define BHh  64            // Bb*Hh
#define Mrows (Lq*Bb)      // 8192
#define SEG  ((size_t)BHh * Lq * HD)     // 8388608
#define ME   ((size_t)Mrows * Ee)        // 8388608
#define EE   ((size_t)Ee * Ee)           // 1048576

// fp16 operands (plain, single precision-pass; fp32 accumulate everywhere)
__device__ __half g_xf[3 * ME];          // q,k,v activations (prep)
__device__ __half g_wf[4 * EE];          // in_proj_weight (3EE) + out_w (EE)
__device__ __half g_qf[SEG], g_kf[SEG], g_vf[SEG];   // projected Q,K,V (BH,L,HD)
__device__ __half g_of[SEG];             // attention output

typedef unsigned long long u64;

// ---------------------------------------------------------------------------
// helpers
// ---------------------------------------------------------------------------
__device__ __forceinline__ uint32_t smem_u32(const void* p) {
    uint32_t a;
    asm("{ .reg .u64 t; cvta.to.shared.u64 t, %1; cvt.u32.u64 %0, t; }"
        : "=r"(a) : "l"(p));
    return a;
}
#define CP16(dst, src) asm volatile("cp.async.cg.shared.global [%0], [%1], 16;" :: "r"(dst), "l"(src))
#define CP_COMMIT()    asm volatile("cp.async.commit_group;" ::: "memory")
#define CP_WAIT(n)     asm volatile("cp.async.wait_group %0;" :: "n"(n) : "memory")

__device__ __forceinline__ void mma_f16(float* c, const uint32_t* a, const uint32_t* b) {
    asm volatile(
        "mma.sync.aligned.m16n8k16.row.col.f32.f16.f16.f32 "
        "{%0,%1,%2,%3}, {%4,%5,%6,%7}, {%8,%9}, {%0,%1,%2,%3};"
        : "+f"(c[0]), "+f"(c[1]), "+f"(c[2]), "+f"(c[3])
        : "r"(a[0]), "r"(a[1]), "r"(a[2]), "r"(a[3]), "r"(b[0]), "r"(b[1]));
}

__device__ __forceinline__ uint32_t pack_h2(float f0, float f1) {
    __half2 h = __floats2half2_rn(f0, f1);
    return *(uint32_t*)&h;
}
__device__ __forceinline__ uint32_t geth(const uint2& v, int j) {
    uint32_t w = (j >> 1) ? v.y : v.x;
    return (j & 1) ? (w >> 16) : (w & 0xffffu);
}

// ---------------------------------------------------------------------------
// prep: convert activations + weights to fp16. One float4 per thread.
// ---------------------------------------------------------------------------
#define NX4 ((3 * ME + 4 * EE) / 4)
__global__ __launch_bounds__(256)
void prep_kernel(const float* __restrict__ q, const float* __restrict__ k,
                 const float* __restrict__ v, const float* __restrict__ w,
                 const float* __restrict__ ow)
{
    size_t i4 = (size_t)blockIdx.x * 256 + threadIdx.x;
    if (i4 >= NX4) return;
    size_t base = i4 * 4;
    const float* src;
    __half* dst;
    if (base < 3 * ME) {
        size_t z = base / ME, off = base - z * ME;
        src = (z == 0 ? q : z == 1 ? k : v) + off;
        dst = g_xf + base;
    } else {
        size_t off = base - 3 * ME;
        src = (off < 3 * EE) ? (w + off) : (ow + (off - 3 * EE));
        dst = g_wf + off;
    }
    float4 f = *(const float4*)src;
    *(uint2*)dst = make_uint2(pack_h2(f.x, f.y), pack_h2(f.z, f.w));
}

// ---------------------------------------------------------------------------
// GEMM on mma.sync fp16 (single pass, fp32 acc). CTA 128x128, K-step 32,
// 2-stage cp.async, one barrier per K-step, smem 40KB -> 2 CTAs/SM.
// MODE 0: QKV projection (writes fp16 Q,K,V), MODE 1: out projection.
// ---------------------------------------------------------------------------
#define GROW  80                     // 32 fp16 = 64B data + 16B pad
#define TP    (128 * GROW)           // 10240
#define STG   (2 * TP)               // 20480 (A + B)
#define SMEM_T (2 * STG)             // 40960
#define NIT   32                     // 1024 / 32

template<int MODE>
__global__ __launch_bounds__(256, 2)
void gemm_tc(const float* __restrict__ bias, float* __restrict__ outp)
{
    extern __shared__ __align__(128) char smem[];
    const uint32_t sbase = smem_u32(smem);

    const int z   = (MODE == 0) ? blockIdx.z : 0;
    const int bm  = blockIdx.y * 128;
    const int bn  = blockIdx.x * 128;
    const int tid = threadIdx.x;
    const int wid  = tid >> 5;
    const int lane = tid & 31;
    const int wm = wid & 3;
    const int wn = wid >> 2;

    const int r    = tid >> 1;       // 0..127 tile row
    const int half = tid & 1;        // 16-element half of a 32-col row

    const __half* a_row;
    if (MODE == 0) {
        a_row = g_xf + (size_t)z * ME + (size_t)(bm + r) * Ee + half * 16;
    } else {
        const int mrow = bm + r;
        const int lA = mrow >> 2, bA = mrow & 3;
        a_row = g_of + ((size_t)bA * Hh * Lq + lA) * HD + half * 16;
    }
    const __half* b_row = g_wf + (size_t)((MODE == 0 ? z * Ee : 3 * Ee) + bn + r) * Ee + half * 16;

    const uint32_t dst_r = sbase + r * GROW + half * 32;

    float acc[2][8][4];
#pragma unroll
    for (int i = 0; i < 2; i++)
#pragma unroll
        for (int j = 0; j < 8; j++)
#pragma unroll
            for (int t = 0; t < 4; t++) acc[i][j][t] = 0.0f;

    auto load_stage = [&](int it, int s) {
        const uint32_t d = dst_r + s * STG;
        const size_t aoff = (MODE == 0)
            ? (size_t)it * 32
            : (size_t)(it >> 1) * ((size_t)Lq * HD) + (size_t)(it & 1) * 32;
        const __half* pa = a_row + aoff;
        const __half* pb = b_row + (size_t)it * 32;
        CP16(d + 0,       pa); CP16(d + 16,       pa + 8);
        CP16(d + TP + 0,  pb); CP16(d + TP + 16,  pb + 8);
    };

    const int g  = lane >> 2;
    const int tc = lane & 3;

    load_stage(0, 0); CP_COMMIT();

    for (int it = 0; it < NIT; it++) {
        CP_WAIT(0);
        __syncthreads();
        if (it + 1 < NIT) { load_stage(it + 1, (it + 1) & 1); CP_COMMIT(); }

        const char* sa = smem + (it & 1) * STG;
        const char* sbm = sa + TP;

#pragma unroll
        for (int ks = 0; ks < 2; ks++) {
            const int cbyte = ks * 32 + tc * 4;
            uint32_t ah[2][4];
#pragma unroll
            for (int mt = 0; mt < 2; mt++) {
                const int r0 = wm * 32 + mt * 16 + g;
                const char* ph = sa + r0 * GROW + cbyte;
                ah[mt][0] = *(const uint32_t*)(ph);
                ah[mt][1] = *(const uint32_t*)(ph + 8 * GROW);
                ah[mt][2] = *(const uint32_t*)(ph + 16);
                ah[mt][3] = *(const uint32_t*)(ph + 8 * GROW + 16);
            }
#pragma unroll
            for (int nt = 0; nt < 8; nt++) {
                const int rn = wn * 64 + nt * 8 + g;
                const char* pbh = sbm + rn * GROW + cbyte;
                uint32_t bh[2];
                bh[0] = *(const uint32_t*)(pbh);
                bh[1] = *(const uint32_t*)(pbh + 16);
#pragma unroll
                for (int mt = 0; mt < 2; mt++)
                    mma_f16(acc[mt][nt], ah[mt], bh);
            }
        }
    }

    const float scale = (MODE == 0 && z == 0) ? 0.125f : 1.0f;
#pragma unroll
    for (int mt = 0; mt < 2; mt++) {
#pragma unroll
        for (int half_m = 0; half_m < 2; half_m++) {
            const int m = bm + wm * 32 + mt * 16 + g + half_m * 8;
#pragma unroll
            for (int nt = 0; nt < 8; nt++) {
                const int n = bn + wn * 64 + nt * 8 + tc * 2;
                const float c0 = acc[mt][nt][half_m * 2 + 0];
                const float c1 = acc[mt][nt][half_m * 2 + 1];
                if (MODE == 0) {
                    const int l = m >> 2, b = m & 3;
                    const int h = n >> 6, d = n & 63;
                    float v0 = scale * (c0 + bias[z * Ee + n]);
                    float v1 = scale * (c1 + bias[z * Ee + n + 1]);
                    size_t addr = ((size_t)(b * Hh + h) * Lq + l) * HD + d;
                    __half* dstp = (z == 0) ? g_qf : (z == 1) ? g_kf : g_vf;
                    *(uint32_t*)&dstp[addr] = pack_h2(v0, v1);
                } else {
                    float2 t;
                    t.x = c0 + bias[n];
                    t.y = c1 + bias[n + 1];
                    *(float2*)&outp[(size_t)m * Ee + n] = t;
                }
            }
        }
    }
}

// ---------------------------------------------------------------------------
// Flash attention, all-fp16 MMA (fp32 acc + fp32 softmax). K-tile 64,
// 2-stage pipeline, smem 37KB -> 2 CTAs/SM.
// K token-major (144B rows); V transposed hd-major (144B rows).
// ---------------------------------------------------------------------------
#define TKT    64
#define KROW   144
#define VTROW  144
#define SM_K   0
#define SM_VT  (SM_K + TKT * KROW)        // 9216
#define AT_STG (SM_VT + 64 * VTROW)       // 18432 per stage
#define SM_ATTN (2 * AT_STG)              // 36864

__global__ __launch_bounds__(256, 2)
void attn_mma()
{
    extern __shared__ __align__(128) char smem[];
    const uint32_t sb = smem_u32(smem);

    const int head = blockIdx.y;
    const int q0   = blockIdx.x * 128;
    const int tid  = threadIdx.x;
    const int wid  = tid >> 5;
    const int lane = tid & 31;
    const int g    = lane >> 2;
    const int tc   = lane & 3;

    // Q fragments in registers (per warp: 16 rows x 64 hd), fp16
    uint32_t qa[4][4];
    {
        const size_t r0 = (size_t)head * Lq + q0 + wid * 16 + g;
        const size_t r1 = r0 + 8;
#pragma unroll
        for (int ks = 0; ks < 4; ks++) {
            const int c0 = ks * 16 + tc * 2;
            qa[ks][0] = *(const uint32_t*)(g_qf + r0 * HD + c0);
            qa[ks][1] = *(const uint32_t*)(g_qf + r1 * HD + c0);
            qa[ks][2] = *(const uint32_t*)(g_qf + r0 * HD + c0 + 8);
            qa[ks][3] = *(const uint32_t*)(g_qf + r1 * HD + c0 + 8);
        }
    }

    float O[8][4];
#pragma unroll
    for (int i = 0; i < 8; i++)
#pragma unroll
        for (int j = 0; j < 4; j++) O[i][j] = 0.0f;
    float m0 = -1e30f, m1 = -1e30f, l0 = 0.0f, l1 = 0.0f;

    // coop-load assignments
    const int kr = tid >> 2;          // 0..63 K rows
    const int kq = tid & 3;           // 32B quarter
    const int tb = (tid & 15) * 4;    // V token block (4 tokens)
    const int hb = (tid >> 4) * 4;    // V hd block (4 dims)

    auto load_k = [&](int kt, int s) {
        const uint32_t dk = sb + s * AT_STG + SM_K + kr * KROW + kq * 32;
        const size_t src = ((size_t)head * Lq + kt + kr) * HD + kq * 16;
        CP16(dk, g_kf + src); CP16(dk + 16, g_kf + src + 8);
        CP_COMMIT();
    };
    auto load_v = [&](int kt, uint2* vv) {
#pragma unroll
        for (int t = 0; t < 4; t++)
            vv[t] = *(const uint2*)(g_vf + ((size_t)head * Lq + kt + tb + t) * HD + hb);
    };
    auto store_v = [&](int s, const uint2* vv) {
        const uint32_t vdst = sb + s * AT_STG + SM_VT;
#pragma unroll
        for (int j = 0; j < 4; j++) {
            uint32_t p01 = geth(vv[0], j) | (geth(vv[1], j) << 16);
            uint32_t p23 = geth(vv[2], j) | (geth(vv[3], j) << 16);
            const uint32_t a = vdst + (hb + j) * VTROW + tb * 2;
            asm volatile("st.shared.b32 [%0], %1;" :: "r"(a), "r"(p01) : "memory");
            asm volatile("st.shared.b32 [%0], %1;" :: "r"(a + 4), "r"(p23) : "memory");
        }
    };

    // prologue: tile 0 into stage 0
    {
        uint2 vv[4];
        load_k(0, 0);
        load_v(0, vv);
        store_v(0, vv);
    }

    const int NTILE = Lq / TKT;      // 32
    for (int t = 0; t < NTILE; t++) {
        CP_WAIT(0);
        __syncthreads();
        const int cur = t & 1;
        const int nxt = (t + 1) & 1;
        if (t + 1 < NTILE) load_k((t + 1) * TKT, nxt);

        const char* skh = smem + cur * AT_STG + SM_K;

        // S = Q K^T (8 ntiles of 8 tokens), fp16 single pass
        float s[8][4];
#pragma unroll
        for (int nt = 0; nt < 8; nt++) {
            float c[4] = {0.f, 0.f, 0.f, 0.f};
#pragma unroll
            for (int ks = 0; ks < 4; ks++) {
                const char* pb = skh + (nt * 8 + g) * KROW + ks * 32 + tc * 4;
                uint32_t bh[2];
                bh[0] = *(const uint32_t*)(pb);
                bh[1] = *(const uint32_t*)(pb + 16);
                mma_f16(c, qa[ks], bh);
            }
            s[nt][0] = c[0]; s[nt][1] = c[1]; s[nt][2] = c[2]; s[nt][3] = c[3];
        }

        // prefetch V of next tile into registers
        uint2 vv[4];
        if (t + 1 < NTILE) load_v((t + 1) * TKT, vv);

        // online softmax (quad-reduced row max)
        float tm0 = -1e30f, tm1 = -1e30f;
#pragma unroll
        for (int nt = 0; nt < 8; nt++) {
            tm0 = fmaxf(tm0, fmaxf(s[nt][0], s[nt][1]));
            tm1 = fmaxf(tm1, fmaxf(s[nt][2], s[nt][3]));
        }
        tm0 = fmaxf(tm0, __shfl_xor_sync(0xffffffffu, tm0, 1));
        tm0 = fmaxf(tm0, __shfl_xor_sync(0xffffffffu, tm0, 2));
        tm1 = fmaxf(tm1, __shfl_xor_sync(0xffffffffu, tm1, 1));
        tm1 = fmaxf(tm1, __shfl_xor_sync(0xffffffffu, tm1, 2));

        const float nm0 = fmaxf(m0, tm0);
        const float nm1 = fmaxf(m1, tm1);
        const float cor0 = __expf(m0 - nm0);
        const float cor1 = __expf(m1 - nm1);
        m0 = nm0; m1 = nm1;
        l0 *= cor0; l1 *= cor1;
#pragma unroll
        for (int nt = 0; nt < 8; nt++) {
            O[nt][0] *= cor0; O[nt][1] *= cor0;
            O[nt][2] *= cor1; O[nt][3] *= cor1;
        }

        // exp + pack P fragments as fp16 (C-frag layout == A-frag layout)
        uint32_t pa[4][4];
#pragma unroll
        for (int ks = 0; ks < 4; ks++) {
            const float p0 = __expf(s[2 * ks][0] - m0);
            const float p1 = __expf(s[2 * ks][1] - m0);
            const float p2 = __expf(s[2 * ks][2] - m1);
            const float p3 = __expf(s[2 * ks][3] - m1);
            const float p4 = __expf(s[2 * ks + 1][0] - m0);
            const float p5 = __expf(s[2 * ks + 1][1] - m0);
            const float p6 = __expf(s[2 * ks + 1][2] - m1);
            const float p7 = __expf(s[2 * ks + 1][3] - m1);
            l0 += p0 + p1 + p4 + p5;
            l1 += p2 + p3 + p6 + p7;
            pa[ks][0] = pack_h2(p0, p1);
            pa[ks][1] = pack_h2(p2, p3);
            pa[ks][2] = pack_h2(p4, p5);
            pa[ks][3] = pack_h2(p6, p7);
        }

        // O += P V (fp16 single pass: 8 hd ntiles x 4 ksteps of 16 tokens)
        const char* svt = smem + cur * AT_STG + SM_VT;
#pragma unroll
        for (int nt = 0; nt < 8; nt++) {
#pragma unroll
            for (int ks = 0; ks < 4; ks++) {
                const char* pv = svt + (nt * 8 + g) * VTROW + ks * 32 + tc * 4;
                uint32_t v2[2];
                v2[0] = *(const uint32_t*)(pv);
                v2[1] = *(const uint32_t*)(pv + 16);
                mma_f16(O[nt], pa[ks], v2);
            }
        }

        // scatter prefetched V into next stage (visible after next barrier)
        if (t + 1 < NTILE) store_v(nxt, vv);
    }

    // finalize: quad-reduce l, normalize, write fp16 O
    l0 += __shfl_xor_sync(0xffffffffu, l0, 1);
    l0 += __shfl_xor_sync(0xffffffffu, l0, 2);
    l1 += __shfl_xor_sync(0xffffffffu, l1, 1);
    l1 += __shfl_xor_sync(0xffffffffu, l1, 2);
    const float inv0 = 1.0f / l0;
    const float inv1 = 1.0f / l1;

    const size_t r0 = (size_t)head * Lq + q0 + wid * 16 + g;
    const size_t r1 = r0 + 8;
#pragma unroll
    for (int nt = 0; nt < 8; nt++) {
        const int col = nt * 8 + tc * 2;
        *(uint32_t*)&g_of[r0 * HD + col] = pack_h2(O[nt][0] * inv0, O[nt][1] * inv0);
        *(uint32_t*)&g_of[r1 * HD + col] = pack_h2(O[nt][2] * inv1, O[nt][3] * inv1);
    }
}

// ---------------------------------------------------------------------------
// Launch
// Inputs: 0=q, 1=k, 2=v, 3=in_proj_weight, 4=in_proj_bias, 5=out_w, 6=out_b
// ---------------------------------------------------------------------------
extern "C" void kernel_launch(void* const* d_in, const int* in_sizes, int n_in,
                              void* d_out, int out_size)
{
    const float* q  = (const float*)d_in[0];
    const float* k  = (const float*)d_in[1];
    const float* v  = (const float*)d_in[2];
    const float* w  = (const float*)d_in[3];
    const float* bi = (const float*)d_in[4];
    const float* ow = (const float*)d_in[5];
    const float* ob = (const float*)d_in[6];
    float* out = (float*)d_out;

    static bool configured = false;
    if (!configured) {
        cudaFuncSetAttribute(gemm_tc<0>, cudaFuncAttributeMaxDynamicSharedMemorySize, SMEM_T);
        cudaFuncSetAttribute(gemm_tc<1>, cudaFuncAttributeMaxDynamicSharedMemorySize, SMEM_T);
        cudaFuncSetAttribute(attn_mma,   cudaFuncAttributeMaxDynamicSharedMemorySize, SM_ATTN);
        configured = true;
    }

    prep_kernel<<<(unsigned)((NX4 + 255) / 256), 256>>>(q, k, v, w, ow);

    dim3 gp(Ee / 128, Mrows / 128, 3);
    gemm_tc<0><<<gp, 256, SMEM_T>>>(bi, nullptr);

    dim3 ga(Lq / 128, BHh);
    attn_mma<<<ga, 256, SM_ATTN>>>();

    dim3 go(Ee / 128, Mrows / 128);
    gemm_tc<1><<<go, 256, SMEM_T>>>(ob, out);
}